// round 8
// baseline (speedup 1.0000x reference)
#include <cuda_runtime.h>
#include <math.h>

#define NN 100000
#define NE 1000000
#define HD 128
#define OD 40

// ---------------- scratch (static device globals; no allocations) -----------
__device__ float g_h  [NN * HD];   // GEMM output / per-layer h
__device__ float g_agg[NN * HD];   // aggregation output -> next layer input
__device__ float g_wt [HD * HD];   // transposed weight
__device__ float g_ei [NN];
__device__ float g_ej [NN];
__device__ float g_mx [NN];
__device__ float g_den[NN];
__device__ float g_ex [NE];
__device__ int   g_is64;

// ---------------- edge dtype detection (int64 vs int32 hedge) ---------------
__global__ void k_detect(const int* __restrict__ e32) {
    __shared__ int bad;
    if (threadIdx.x == 0) bad = 0;
    __syncthreads();
    int v = 0;
    for (int i = threadIdx.x; i < 1024; i += blockDim.x) v |= e32[2 * i + 1];
    if (v) atomicOr(&bad, 1);
    __syncthreads();
    if (threadIdx.x == 0) g_is64 = (bad == 0) ? 1 : 0;
}

__device__ __forceinline__ void load_edge(const void* eidx, int e, int& s, int& d) {
    if (g_is64) {
        const long long* p = (const long long*)eidx;
        s = (int)p[e];
        d = (int)p[NE + e];
    } else {
        const int* p = (const int*)eidx;
        s = p[e];
        d = p[NE + e];
    }
}

// ---------------- W^T precompute ---------------------------------------------
__global__ void k_transpose(const float* __restrict__ W, float* __restrict__ Wt) {
    int i = blockIdx.x * blockDim.x + threadIdx.x;   // 16384
    if (i >= HD * HD) return;
    int c = i >> 7, k = i & 127;                     // W[c][k]
    Wt[k * HD + c] = W[i];
}

// ---------------- GEMM: Y[m][c] = sum_k X[m][k] * Wt[k][c] + bias[c] ---------
// block: 256 threads, tile 128 rows x 128 cols, K=128 fully resident in smem.
__global__ void k_gemm(const float* __restrict__ X, const float* __restrict__ Wt,
                       const float* __restrict__ bias, float* __restrict__ Y, int M) {
    extern __shared__ float sm[];
    float (*As)[132] = (float(*)[132])sm;                   // 128 x 132
    float (*Ws)[128] = (float(*)[128])(sm + 128 * 132);     // 128 x 128
    int tid = threadIdx.x;
    int m0  = blockIdx.x * 128;

    // copy Wt -> Ws (straight vectorized copy; [k][c] layout)
    {
        const float4* src = (const float4*)Wt;
        float4* dst = (float4*)&Ws[0][0];
        #pragma unroll
        for (int i = tid; i < HD * HD / 4; i += 256) dst[i] = src[i];
    }
    // copy X tile (row-major, padded rows)
    for (int i = tid; i < 128 * 32; i += 256) {
        int r = i >> 5, c4 = i & 31;
        float4 v = make_float4(0.f, 0.f, 0.f, 0.f);
        if (m0 + r < M) v = *(const float4*)(X + (size_t)(m0 + r) * HD + c4 * 4);
        *(float4*)(&As[r][c4 * 4]) = v;
    }
    __syncthreads();

    int tx = tid & 15, ty = tid >> 4;
    float acc[8][8];
    #pragma unroll
    for (int i = 0; i < 8; i++)
        #pragma unroll
        for (int j = 0; j < 8; j++) acc[i][j] = 0.f;

    #pragma unroll 4
    for (int k = 0; k < 128; k++) {
        float a[8], b[8];
        #pragma unroll
        for (int i = 0; i < 8; i++) a[i] = As[ty + 16 * i][k];
        #pragma unroll
        for (int j = 0; j < 8; j++) b[j] = Ws[k][tx + 16 * j];
        #pragma unroll
        for (int i = 0; i < 8; i++)
            #pragma unroll
            for (int j = 0; j < 8; j++) acc[i][j] = fmaf(a[i], b[j], acc[i][j]);
    }

    #pragma unroll
    for (int i = 0; i < 8; i++) {
        int m = m0 + ty + 16 * i;
        if (m >= M) continue;
        #pragma unroll
        for (int j = 0; j < 8; j++) {
            int c = tx + 16 * j;
            Y[(size_t)m * HD + c] = acc[i][j] + bias[c];
        }
    }
}

// ---------------- per-node prep: ei/ej dots, init mx/den, zero agg -----------
__global__ void k_prep(const float* __restrict__ h, const float* __restrict__ att) {
    int lane = threadIdx.x & 31;
    int wid  = (blockIdx.x * blockDim.x + threadIdx.x) >> 5;
    int nw   = (gridDim.x * blockDim.x) >> 5;
    float4 ai = *(const float4*)(att + lane * 4);
    float4 aj = *(const float4*)(att + HD + lane * 4);
    const float4 z = make_float4(0.f, 0.f, 0.f, 0.f);
    for (int n = wid; n < NN; n += nw) {
        float4 hv = *(const float4*)(h + (size_t)n * HD + lane * 4);
        float si = hv.x * ai.x + hv.y * ai.y + hv.z * ai.z + hv.w * ai.w;
        float sj = hv.x * aj.x + hv.y * aj.y + hv.z * aj.z + hv.w * aj.w;
        #pragma unroll
        for (int o = 16; o; o >>= 1) {
            si += __shfl_xor_sync(0xffffffffu, si, o);
            sj += __shfl_xor_sync(0xffffffffu, sj, o);
        }
        if (lane == 0) {
            g_ei[n] = si;
            g_ej[n] = sj;
            g_mx[n] = -INFINITY;
            g_den[n] = 0.f;
        }
        *(float4*)(g_agg + (size_t)n * HD + lane * 4) = z;
    }
}

// ---------------- edge pass 1: e = lrelu(ei[d]+ej[s]); segment max ----------
__global__ void k_e1(const void* __restrict__ eidx) {
    int e = blockIdx.x * blockDim.x + threadIdx.x;
    if (e >= NE) return;
    int s, d;
    load_edge(eidx, e, s, d);
    float v = g_ei[d] + g_ej[s];
    v = v > 0.f ? v : 0.2f * v;
    g_ex[e] = v;
    if (v >= 0.f) atomicMax((int*)(g_mx + d), __float_as_int(v));
    else          atomicMin((unsigned int*)(g_mx + d), __float_as_uint(v));
}

// ---------------- edge pass 2: ex = exp(e - mx[d]); segment sum -------------
__global__ void k_e2(const void* __restrict__ eidx) {
    int e = blockIdx.x * blockDim.x + threadIdx.x;
    if (e >= NE) return;
    int s, d;
    load_edge(eidx, e, s, d);
    float v = expf(g_ex[e] - g_mx[d]);
    g_ex[e] = v;
    atomicAdd(g_den + d, v);
}

// ---------------- edge pass 3: agg[d] += h[s] * (ex/den[d])  (warp/edge) ----
__global__ void k_e3(const void* __restrict__ eidx, const float* __restrict__ h) {
    int lane = threadIdx.x & 31;
    int e = (blockIdx.x * blockDim.x + threadIdx.x) >> 5;
    if (e >= NE) return;
    int s, d;
    load_edge(eidx, e, s, d);
    float alpha = g_ex[e] / g_den[d];
    float4 hv = *(const float4*)(h + (size_t)s * HD + lane * 4);
    float* p = g_agg + (size_t)d * HD + lane * 4;
    asm volatile("red.global.add.v4.f32 [%0], {%1, %2, %3, %4};"
                 :: "l"(p), "f"(hv.x * alpha), "f"(hv.y * alpha),
                    "f"(hv.z * alpha), "f"(hv.w * alpha)
                 : "memory");
}

// ---------------- finalize: agg = relu(agg + bias) (elementwise) ------------
__global__ void k_finalize(const float* __restrict__ bias) {
    int i = blockIdx.x * blockDim.x + threadIdx.x;    // float4 elements
    if (i >= NN * HD / 4) return;
    float4 v = ((float4*)g_agg)[i];
    int c4 = i & 31;
    float4 b = *(const float4*)(bias + c4 * 4);
    v.x = fmaxf(v.x + b.x, 0.f);
    v.y = fmaxf(v.y + b.y, 0.f);
    v.z = fmaxf(v.z + b.z, 0.f);
    v.w = fmaxf(v.w + b.w, 0.f);
    ((float4*)g_agg)[i] = v;
}

// ---------------- output head: y = t@Wp2^T + bp2; log_softmax ---------------
__global__ void k_out(const float* __restrict__ t, const float* __restrict__ Wp2,
                      const float* __restrict__ bp2, float* __restrict__ out) {
    __shared__ float w2s[OD * HD];
    __shared__ float b2s[OD];
    int tid = threadIdx.x;
    for (int i = tid; i < OD * HD / 4; i += blockDim.x)
        ((float4*)w2s)[i] = ((const float4*)Wp2)[i];
    if (tid < OD) b2s[tid] = bp2[tid];
    __syncthreads();

    int lane = tid & 31;
    int wid  = (blockIdx.x * blockDim.x + tid) >> 5;
    int nw   = (gridDim.x * blockDim.x) >> 5;

    for (int n = wid; n < NN; n += nw) {
        float4 tv = *(const float4*)(t + (size_t)n * HD + lane * 4);
        float ya = 0.f, yb = -INFINITY;
        for (int o = 0; o < OD; o++) {
            const float* wr = w2s + o * HD + lane * 4;
            float4 wv = *(const float4*)wr;
            float p = tv.x * wv.x + tv.y * wv.y + tv.z * wv.z + tv.w * wv.w;
            #pragma unroll
            for (int off = 16; off; off >>= 1) p += __shfl_xor_sync(0xffffffffu, p, off);
            float y = p + b2s[o];
            if (o == lane)      ya = y;
            if (o == lane + 32) yb = y;
        }
        // max over 40 logits (lanes >= 8 have no second logit)
        float cand = fmaxf(ya, lane < 8 ? yb : -INFINITY);
        #pragma unroll
        for (int off = 16; off; off >>= 1)
            cand = fmaxf(cand, __shfl_xor_sync(0xffffffffu, cand, off));
        float m = cand;
        float sp = expf(ya - m) + (lane < 8 ? expf(yb - m) : 0.f);
        #pragma unroll
        for (int off = 16; off; off >>= 1) sp += __shfl_xor_sync(0xffffffffu, sp, off);
        float ls = logf(sp);
        out[(size_t)n * OD + lane] = ya - m - ls;
        if (lane < 8) out[(size_t)n * OD + 32 + lane] = yb - m - ls;
    }
}

// ---------------- orchestration ---------------------------------------------
static void* sym_addr(const void* sym) {
    void* p = nullptr;
    cudaGetSymbolAddress(&p, sym);
    return p;
}

extern "C" void kernel_launch(void* const* d_in, const int* in_sizes, int n_in,
                              void* d_out, int out_size) {
    const float* x     = (const float*)d_in[0];
    const void*  eidx  = d_in[1];
    const float* W1    = (const float*)d_in[2];
    const float* b1    = (const float*)d_in[3];
    const float* att1  = (const float*)d_in[4];
    const float* bias1 = (const float*)d_in[5];
    const float* W2    = (const float*)d_in[6];
    const float* b2    = (const float*)d_in[7];
    const float* att2  = (const float*)d_in[8];
    const float* bias2 = (const float*)d_in[9];
    const float* Wp1   = (const float*)d_in[10];
    const float* bp1   = (const float*)d_in[11];
    const float* Wp2   = (const float*)d_in[12];
    const float* bp2   = (const float*)d_in[13];
    float* out = (float*)d_out;

    float* p_h   = (float*)sym_addr(g_h);
    float* p_agg = (float*)sym_addr(g_agg);
    float* p_wt  = (float*)sym_addr(g_wt);

    const int GEMM_SMEM = (128 * 132 + 128 * 128) * 4;
    cudaFuncSetAttribute(k_gemm, cudaFuncAttributeMaxDynamicSharedMemorySize, GEMM_SMEM);

    const int gemm_blocks = (NN + 127) / 128;        // 782
    const int edge_blocks = (NE + 255) / 256;        // 3907
    const int e3_blocks   = NE / 8;                  // 125000 (warp per edge)

    k_detect<<<1, 256>>>((const int*)eidx);

    // ---- layer 1 ----
    k_transpose<<<64, 256>>>(W1, p_wt);
    k_gemm<<<gemm_blocks, 256, GEMM_SMEM>>>(x, p_wt, b1, p_h, NN);
    k_prep<<<1024, 256>>>(p_h, att1);
    k_e1<<<edge_blocks, 256>>>(eidx);
    k_e2<<<edge_blocks, 256>>>(eidx);
    k_e3<<<e3_blocks, 256>>>(eidx, p_h);
    k_finalize<<<(NN * HD / 4 + 255) / 256, 256>>>(bias1);

    // ---- layer 2 ----
    k_transpose<<<64, 256>>>(W2, p_wt);
    k_gemm<<<gemm_blocks, 256, GEMM_SMEM>>>(p_agg, p_wt, b2, p_h, NN);
    k_prep<<<1024, 256>>>(p_h, att2);
    k_e1<<<edge_blocks, 256>>>(eidx);
    k_e2<<<edge_blocks, 256>>>(eidx);
    k_e3<<<e3_blocks, 256>>>(eidx, p_h);
    k_finalize<<<(NN * HD / 4 + 255) / 256, 256>>>(bias2);

    // ---- projection head ----
    k_transpose<<<64, 256>>>(Wp1, p_wt);
    k_gemm<<<gemm_blocks, 256, GEMM_SMEM>>>(p_agg, p_wt, bp1, p_h, NN);
    k_out<<<2048, 256>>>(p_h, Wp2, bp2, out);
}

// round 9
// speedup vs baseline: 1.0086x; 1.0086x over previous
#include <cuda_runtime.h>
#include <math.h>

#define NN 100000
#define NE 1000000
#define HD 128
#define OD 40

// ---------------- scratch (static device globals; no allocations) -----------
__device__ float g_h  [NN * HD];   // GEMM output / per-layer h
__device__ float g_agg[NN * HD];   // aggregation output -> next layer input
__device__ float g_wt [HD * HD];   // transposed weight
__device__ float g_ei [NN];
__device__ float g_ej [NN];
__device__ float g_mx [NN];
__device__ float g_den[NN];
__device__ float g_ex [NE];
__device__ int   g_is64;

// ---------------- edge dtype detection (int64 vs int32 hedge) ---------------
__global__ void k_detect(const int* __restrict__ e32) {
    __shared__ int bad;
    if (threadIdx.x == 0) bad = 0;
    __syncthreads();
    int v = 0;
    for (int i = threadIdx.x; i < 1024; i += blockDim.x) v |= e32[2 * i + 1];
    if (v) atomicOr(&bad, 1);
    __syncthreads();
    if (threadIdx.x == 0) g_is64 = (bad == 0) ? 1 : 0;
}

__device__ __forceinline__ void load_edge(const void* eidx, int e, int& s, int& d) {
    if (g_is64) {
        const long long* p = (const long long*)eidx;
        s = (int)p[e];
        d = (int)p[NE + e];
    } else {
        const int* p = (const int*)eidx;
        s = p[e];
        d = p[NE + e];
    }
}

// ---------------- W^T precompute ---------------------------------------------
__global__ void k_transpose(const float* __restrict__ W, float* __restrict__ Wt) {
    int i = blockIdx.x * blockDim.x + threadIdx.x;   // 16384
    if (i >= HD * HD) return;
    int c = i >> 7, k = i & 127;                     // W[c][k]
    Wt[k * HD + c] = W[i];
}

// ---------------- GEMM: Y[m][c] = sum_k X[m][k] * Wt[k][c] + bias[c] ---------
// block: 256 threads, tile 128 rows x 128 cols, K=128 fully resident in smem.
__global__ void k_gemm(const float* __restrict__ X, const float* __restrict__ Wt,
                       const float* __restrict__ bias, float* __restrict__ Y, int M) {
    extern __shared__ float sm[];
    float (*As)[132] = (float(*)[132])sm;                   // 128 x 132
    float (*Ws)[128] = (float(*)[128])(sm + 128 * 132);     // 128 x 128
    int tid = threadIdx.x;
    int m0  = blockIdx.x * 128;

    // copy Wt -> Ws (straight vectorized copy; [k][c] layout)
    {
        const float4* src = (const float4*)Wt;
        float4* dst = (float4*)&Ws[0][0];
        #pragma unroll
        for (int i = tid; i < HD * HD / 4; i += 256) dst[i] = src[i];
    }
    // copy X tile (row-major, padded rows)
    for (int i = tid; i < 128 * 32; i += 256) {
        int r = i >> 5, c4 = i & 31;
        float4 v = make_float4(0.f, 0.f, 0.f, 0.f);
        if (m0 + r < M) v = *(const float4*)(X + (size_t)(m0 + r) * HD + c4 * 4);
        *(float4*)(&As[r][c4 * 4]) = v;
    }
    __syncthreads();

    int tx = tid & 15, ty = tid >> 4;
    float acc[8][8];
    #pragma unroll
    for (int i = 0; i < 8; i++)
        #pragma unroll
        for (int j = 0; j < 8; j++) acc[i][j] = 0.f;

    #pragma unroll 4
    for (int k = 0; k < 128; k++) {
        float a[8], b[8];
        #pragma unroll
        for (int i = 0; i < 8; i++) a[i] = As[ty + 16 * i][k];
        #pragma unroll
        for (int j = 0; j < 8; j++) b[j] = Ws[k][tx + 16 * j];
        #pragma unroll
        for (int i = 0; i < 8; i++)
            #pragma unroll
            for (int j = 0; j < 8; j++) acc[i][j] = fmaf(a[i], b[j], acc[i][j]);
    }

    #pragma unroll
    for (int i = 0; i < 8; i++) {
        int m = m0 + ty + 16 * i;
        if (m >= M) continue;
        #pragma unroll
        for (int j = 0; j < 8; j++) {
            int c = tx + 16 * j;
            Y[(size_t)m * HD + c] = acc[i][j] + bias[c];
        }
    }
}

// ---------------- per-node prep: ei/ej dots, init mx/den, zero agg -----------
__global__ void k_prep(const float* __restrict__ h, const float* __restrict__ att) {
    int lane = threadIdx.x & 31;
    int wid  = (blockIdx.x * blockDim.x + threadIdx.x) >> 5;
    int nw   = (gridDim.x * blockDim.x) >> 5;
    float4 ai = *(const float4*)(att + lane * 4);
    float4 aj = *(const float4*)(att + HD + lane * 4);
    const float4 z = make_float4(0.f, 0.f, 0.f, 0.f);
    for (int n = wid; n < NN; n += nw) {
        float4 hv = *(const float4*)(h + (size_t)n * HD + lane * 4);
        float si = hv.x * ai.x + hv.y * ai.y + hv.z * ai.z + hv.w * ai.w;
        float sj = hv.x * aj.x + hv.y * aj.y + hv.z * aj.z + hv.w * aj.w;
        #pragma unroll
        for (int o = 16; o; o >>= 1) {
            si += __shfl_xor_sync(0xffffffffu, si, o);
            sj += __shfl_xor_sync(0xffffffffu, sj, o);
        }
        if (lane == 0) {
            g_ei[n] = si;
            g_ej[n] = sj;
            g_mx[n] = -INFINITY;
            g_den[n] = 0.f;
        }
        *(float4*)(g_agg + (size_t)n * HD + lane * 4) = z;
    }
}

// ---------------- edge pass 1: e = lrelu(ei[d]+ej[s]); segment max ----------
__global__ void k_e1(const void* __restrict__ eidx) {
    int e = blockIdx.x * blockDim.x + threadIdx.x;
    if (e >= NE) return;
    int s, d;
    load_edge(eidx, e, s, d);
    float v = g_ei[d] + g_ej[s];
    v = v > 0.f ? v : 0.2f * v;
    g_ex[e] = v;
    if (v >= 0.f) atomicMax((int*)(g_mx + d), __float_as_int(v));
    else          atomicMin((unsigned int*)(g_mx + d), __float_as_uint(v));
}

// ---------------- edge pass 2: ex = exp(e - mx[d]); segment sum -------------
__global__ void k_e2(const void* __restrict__ eidx) {
    int e = blockIdx.x * blockDim.x + threadIdx.x;
    if (e >= NE) return;
    int s, d;
    load_edge(eidx, e, s, d);
    float v = expf(g_ex[e] - g_mx[d]);
    g_ex[e] = v;
    atomicAdd(g_den + d, v);
}

// ---------------- edge pass 3: agg[d] += h[s] * (ex/den[d])  (warp/edge) ----
__global__ void k_e3(const void* __restrict__ eidx, const float* __restrict__ h) {
    int lane = threadIdx.x & 31;
    int e = (blockIdx.x * blockDim.x + threadIdx.x) >> 5;
    if (e >= NE) return;
    int s, d;
    load_edge(eidx, e, s, d);
    float alpha = g_ex[e] / g_den[d];
    float4 hv = *(const float4*)(h + (size_t)s * HD + lane * 4);
    float* p = g_agg + (size_t)d * HD + lane * 4;
    asm volatile("red.global.add.v4.f32 [%0], {%1, %2, %3, %4};"
                 :: "l"(p), "f"(hv.x * alpha), "f"(hv.y * alpha),
                    "f"(hv.z * alpha), "f"(hv.w * alpha)
                 : "memory");
}

// ---------------- finalize: agg = relu(agg + bias) (elementwise) ------------
__global__ void k_finalize(const float* __restrict__ bias) {
    int i = blockIdx.x * blockDim.x + threadIdx.x;    // float4 elements
    if (i >= NN * HD / 4) return;
    float4 v = ((float4*)g_agg)[i];
    int c4 = i & 31;
    float4 b = *(const float4*)(bias + c4 * 4);
    v.x = fmaxf(v.x + b.x, 0.f);
    v.y = fmaxf(v.y + b.y, 0.f);
    v.z = fmaxf(v.z + b.z, 0.f);
    v.w = fmaxf(v.w + b.w, 0.f);
    ((float4*)g_agg)[i] = v;
}

// ---------------- output head: y = t@Wp2^T + bp2; log_softmax ---------------
__global__ void k_out(const float* __restrict__ t, const float* __restrict__ Wp2,
                      const float* __restrict__ bp2, float* __restrict__ out) {
    __shared__ float w2s[OD * HD];
    __shared__ float b2s[OD];
    int tid = threadIdx.x;
    for (int i = tid; i < OD * HD / 4; i += blockDim.x)
        ((float4*)w2s)[i] = ((const float4*)Wp2)[i];
    if (tid < OD) b2s[tid] = bp2[tid];
    __syncthreads();

    int lane = tid & 31;
    int wid  = (blockIdx.x * blockDim.x + tid) >> 5;
    int nw   = (gridDim.x * blockDim.x) >> 5;

    for (int n = wid; n < NN; n += nw) {
        float4 tv = *(const float4*)(t + (size_t)n * HD + lane * 4);
        float ya = 0.f, yb = -INFINITY;
        for (int o = 0; o < OD; o++) {
            const float* wr = w2s + o * HD + lane * 4;
            float4 wv = *(const float4*)wr;
            float p = tv.x * wv.x + tv.y * wv.y + tv.z * wv.z + tv.w * wv.w;
            #pragma unroll
            for (int off = 16; off; off >>= 1) p += __shfl_xor_sync(0xffffffffu, p, off);
            float y = p + b2s[o];
            if (o == lane)      ya = y;
            if (o == lane + 32) yb = y;
        }
        // max over 40 logits (lanes >= 8 have no second logit)
        float cand = fmaxf(ya, lane < 8 ? yb : -INFINITY);
        #pragma unroll
        for (int off = 16; off; off >>= 1)
            cand = fmaxf(cand, __shfl_xor_sync(0xffffffffu, cand, off));
        float m = cand;
        float sp = expf(ya - m) + (lane < 8 ? expf(yb - m) : 0.f);
        #pragma unroll
        for (int off = 16; off; off >>= 1) sp += __shfl_xor_sync(0xffffffffu, sp, off);
        float ls = logf(sp);
        out[(size_t)n * OD + lane] = ya - m - ls;
        if (lane < 8) out[(size_t)n * OD + 32 + lane] = yb - m - ls;
    }
}

// ---------------- orchestration ---------------------------------------------
static void* sym_addr(const void* sym) {
    void* p = nullptr;
    cudaGetSymbolAddress(&p, sym);
    return p;
}

extern "C" void kernel_launch(void* const* d_in, const int* in_sizes, int n_in,
                              void* d_out, int out_size) {
    const float* x     = (const float*)d_in[0];
    const void*  eidx  = d_in[1];
    const float* W1    = (const float*)d_in[2];
    const float* b1    = (const float*)d_in[3];
    const float* att1  = (const float*)d_in[4];
    const float* bias1 = (const float*)d_in[5];
    const float* W2    = (const float*)d_in[6];
    const float* b2    = (const float*)d_in[7];
    const float* att2  = (const float*)d_in[8];
    const float* bias2 = (const float*)d_in[9];
    const float* Wp1   = (const float*)d_in[10];
    const float* bp1   = (const float*)d_in[11];
    const float* Wp2   = (const float*)d_in[12];
    const float* bp2   = (const float*)d_in[13];
    float* out = (float*)d_out;

    float* p_h   = (float*)sym_addr(g_h);
    float* p_agg = (float*)sym_addr(g_agg);
    float* p_wt  = (float*)sym_addr(g_wt);

    const int GEMM_SMEM = (128 * 132 + 128 * 128) * 4;
    cudaFuncSetAttribute(k_gemm, cudaFuncAttributeMaxDynamicSharedMemorySize, GEMM_SMEM);

    const int gemm_blocks = (NN + 127) / 128;        // 782
    const int edge_blocks = (NE + 255) / 256;        // 3907
    const int e3_blocks   = NE / 8;                  // 125000 (warp per edge)

    k_detect<<<1, 256>>>((const int*)eidx);

    // ---- layer 1 ----
    k_transpose<<<64, 256>>>(W1, p_wt);
    k_gemm<<<gemm_blocks, 256, GEMM_SMEM>>>(x, p_wt, b1, p_h, NN);
    k_prep<<<1024, 256>>>(p_h, att1);
    k_e1<<<edge_blocks, 256>>>(eidx);
    k_e2<<<edge_blocks, 256>>>(eidx);
    k_e3<<<e3_blocks, 256>>>(eidx, p_h);
    k_finalize<<<(NN * HD / 4 + 255) / 256, 256>>>(bias1);

    // ---- layer 2 ----
    k_transpose<<<64, 256>>>(W2, p_wt);
    k_gemm<<<gemm_blocks, 256, GEMM_SMEM>>>(p_agg, p_wt, b2, p_h, NN);
    k_prep<<<1024, 256>>>(p_h, att2);
    k_e1<<<edge_blocks, 256>>>(eidx);
    k_e2<<<edge_blocks, 256>>>(eidx);
    k_e3<<<e3_blocks, 256>>>(eidx, p_h);
    k_finalize<<<(NN * HD / 4 + 255) / 256, 256>>>(bias2);

    // ---- projection head ----
    k_transpose<<<64, 256>>>(Wp1, p_wt);
    k_gemm<<<gemm_blocks, 256, GEMM_SMEM>>>(p_agg, p_wt, bp1, p_h, NN);
    k_out<<<2048, 256>>>(p_h, Wp2, bp2, out);
}

// round 10
// speedup vs baseline: 1.0107x; 1.0021x over previous
#include <cuda_runtime.h>
#include <math.h>

#define NN 100000
#define NE 1000000
#define HD 128
#define OD 40

// ---------------- scratch (static device globals; no allocations) -----------
__device__ float g_h  [NN * HD];   // GEMM output / per-layer h
__device__ float g_agg[NN * HD];   // aggregation output -> next layer input
__device__ float g_wt [HD * HD];   // transposed weight
__device__ float g_ei [NN];
__device__ float g_ej [NN];
__device__ float g_mx [NN];
__device__ float g_den[NN];
__device__ float g_ex [NE];
__device__ int   g_is64;

// ---------------- edge dtype detection (int64 vs int32 hedge) ---------------
__global__ void k_detect(const int* __restrict__ e32) {
    __shared__ int bad;
    if (threadIdx.x == 0) bad = 0;
    __syncthreads();
    int v = 0;
    for (int i = threadIdx.x; i < 1024; i += blockDim.x) v |= e32[2 * i + 1];
    if (v) atomicOr(&bad, 1);
    __syncthreads();
    if (threadIdx.x == 0) g_is64 = (bad == 0) ? 1 : 0;
}

__device__ __forceinline__ void load_edge(const void* eidx, int e, int& s, int& d) {
    if (g_is64) {
        const long long* p = (const long long*)eidx;
        s = (int)p[e];
        d = (int)p[NE + e];
    } else {
        const int* p = (const int*)eidx;
        s = p[e];
        d = p[NE + e];
    }
}

// ---------------- W^T precompute ---------------------------------------------
__global__ void k_transpose(const float* __restrict__ W, float* __restrict__ Wt) {
    int i = blockIdx.x * blockDim.x + threadIdx.x;   // 16384
    if (i >= HD * HD) return;
    int c = i >> 7, k = i & 127;                     // W[c][k]
    Wt[k * HD + c] = W[i];
}

// ---------------- GEMM: Y[m][c] = sum_k X[m][k] * Wt[k][c] + bias[c] ---------
// block: 256 threads, tile 128 rows x 128 cols, K=128 fully resident in smem.
__global__ void k_gemm(const float* __restrict__ X, const float* __restrict__ Wt,
                       const float* __restrict__ bias, float* __restrict__ Y, int M) {
    extern __shared__ float sm[];
    float (*As)[132] = (float(*)[132])sm;                   // 128 x 132
    float (*Ws)[128] = (float(*)[128])(sm + 128 * 132);     // 128 x 128
    int tid = threadIdx.x;
    int m0  = blockIdx.x * 128;

    // copy Wt -> Ws (straight vectorized copy; [k][c] layout)
    {
        const float4* src = (const float4*)Wt;
        float4* dst = (float4*)&Ws[0][0];
        #pragma unroll
        for (int i = tid; i < HD * HD / 4; i += 256) dst[i] = src[i];
    }
    // copy X tile (row-major, padded rows)
    for (int i = tid; i < 128 * 32; i += 256) {
        int r = i >> 5, c4 = i & 31;
        float4 v = make_float4(0.f, 0.f, 0.f, 0.f);
        if (m0 + r < M) v = *(const float4*)(X + (size_t)(m0 + r) * HD + c4 * 4);
        *(float4*)(&As[r][c4 * 4]) = v;
    }
    __syncthreads();

    int tx = tid & 15, ty = tid >> 4;
    float acc[8][8];
    #pragma unroll
    for (int i = 0; i < 8; i++)
        #pragma unroll
        for (int j = 0; j < 8; j++) acc[i][j] = 0.f;

    #pragma unroll 4
    for (int k = 0; k < 128; k++) {
        float a[8], b[8];
        #pragma unroll
        for (int i = 0; i < 8; i++) a[i] = As[ty + 16 * i][k];
        #pragma unroll
        for (int j = 0; j < 8; j++) b[j] = Ws[k][tx + 16 * j];
        #pragma unroll
        for (int i = 0; i < 8; i++)
            #pragma unroll
            for (int j = 0; j < 8; j++) acc[i][j] = fmaf(a[i], b[j], acc[i][j]);
    }

    #pragma unroll
    for (int i = 0; i < 8; i++) {
        int m = m0 + ty + 16 * i;
        if (m >= M) continue;
        #pragma unroll
        for (int j = 0; j < 8; j++) {
            int c = tx + 16 * j;
            Y[(size_t)m * HD + c] = acc[i][j] + bias[c];
        }
    }
}

// ---------------- per-node prep: ei/ej dots, init mx/den, zero agg -----------
__global__ void k_prep(const float* __restrict__ h, const float* __restrict__ att) {
    int lane = threadIdx.x & 31;
    int wid  = (blockIdx.x * blockDim.x + threadIdx.x) >> 5;
    int nw   = (gridDim.x * blockDim.x) >> 5;
    float4 ai = *(const float4*)(att + lane * 4);
    float4 aj = *(const float4*)(att + HD + lane * 4);
    const float4 z = make_float4(0.f, 0.f, 0.f, 0.f);
    for (int n = wid; n < NN; n += nw) {
        float4 hv = *(const float4*)(h + (size_t)n * HD + lane * 4);
        float si = hv.x * ai.x + hv.y * ai.y + hv.z * ai.z + hv.w * ai.w;
        float sj = hv.x * aj.x + hv.y * aj.y + hv.z * aj.z + hv.w * aj.w;
        #pragma unroll
        for (int o = 16; o; o >>= 1) {
            si += __shfl_xor_sync(0xffffffffu, si, o);
            sj += __shfl_xor_sync(0xffffffffu, sj, o);
        }
        if (lane == 0) {
            g_ei[n] = si;
            g_ej[n] = sj;
            g_mx[n] = -INFINITY;
            g_den[n] = 0.f;
        }
        *(float4*)(g_agg + (size_t)n * HD + lane * 4) = z;
    }
}

// ---------------- edge pass 1: e = lrelu(ei[d]+ej[s]); segment max ----------
__global__ void k_e1(const void* __restrict__ eidx) {
    int e = blockIdx.x * blockDim.x + threadIdx.x;
    if (e >= NE) return;
    int s, d;
    load_edge(eidx, e, s, d);
    float v = g_ei[d] + g_ej[s];
    v = v > 0.f ? v : 0.2f * v;
    g_ex[e] = v;
    if (v >= 0.f) atomicMax((int*)(g_mx + d), __float_as_int(v));
    else          atomicMin((unsigned int*)(g_mx + d), __float_as_uint(v));
}

// ---------------- edge pass 2: ex = exp(e - mx[d]); segment sum -------------
__global__ void k_e2(const void* __restrict__ eidx) {
    int e = blockIdx.x * blockDim.x + threadIdx.x;
    if (e >= NE) return;
    int s, d;
    load_edge(eidx, e, s, d);
    float v = expf(g_ex[e] - g_mx[d]);
    g_ex[e] = v;
    atomicAdd(g_den + d, v);
}

// ---------------- edge pass 3: agg[d] += h[s] * (ex/den[d])  (warp/edge) ----
__global__ void k_e3(const void* __restrict__ eidx, const float* __restrict__ h) {
    int lane = threadIdx.x & 31;
    int e = (blockIdx.x * blockDim.x + threadIdx.x) >> 5;
    if (e >= NE) return;
    int s, d;
    load_edge(eidx, e, s, d);
    float alpha = g_ex[e] / g_den[d];
    float4 hv = *(const float4*)(h + (size_t)s * HD + lane * 4);
    float* p = g_agg + (size_t)d * HD + lane * 4;
    asm volatile("red.global.add.v4.f32 [%0], {%1, %2, %3, %4};"
                 :: "l"(p), "f"(hv.x * alpha), "f"(hv.y * alpha),
                    "f"(hv.z * alpha), "f"(hv.w * alpha)
                 : "memory");
}

// ---------------- finalize: agg = relu(agg + bias) (elementwise) ------------
__global__ void k_finalize(const float* __restrict__ bias) {
    int i = blockIdx.x * blockDim.x + threadIdx.x;    // float4 elements
    if (i >= NN * HD / 4) return;
    float4 v = ((float4*)g_agg)[i];
    int c4 = i & 31;
    float4 b = *(const float4*)(bias + c4 * 4);
    v.x = fmaxf(v.x + b.x, 0.f);
    v.y = fmaxf(v.y + b.y, 0.f);
    v.z = fmaxf(v.z + b.z, 0.f);
    v.w = fmaxf(v.w + b.w, 0.f);
    ((float4*)g_agg)[i] = v;
}

// ---------------- output head: y = t@Wp2^T + bp2; log_softmax ---------------
__global__ void k_out(const float* __restrict__ t, const float* __restrict__ Wp2,
                      const float* __restrict__ bp2, float* __restrict__ out) {
    __shared__ float w2s[OD * HD];
    __shared__ float b2s[OD];
    int tid = threadIdx.x;
    for (int i = tid; i < OD * HD / 4; i += blockDim.x)
        ((float4*)w2s)[i] = ((const float4*)Wp2)[i];
    if (tid < OD) b2s[tid] = bp2[tid];
    __syncthreads();

    int lane = tid & 31;
    int wid  = (blockIdx.x * blockDim.x + tid) >> 5;
    int nw   = (gridDim.x * blockDim.x) >> 5;

    for (int n = wid; n < NN; n += nw) {
        float4 tv = *(const float4*)(t + (size_t)n * HD + lane * 4);
        float ya = 0.f, yb = -INFINITY;
        for (int o = 0; o < OD; o++) {
            const float* wr = w2s + o * HD + lane * 4;
            float4 wv = *(const float4*)wr;
            float p = tv.x * wv.x + tv.y * wv.y + tv.z * wv.z + tv.w * wv.w;
            #pragma unroll
            for (int off = 16; off; off >>= 1) p += __shfl_xor_sync(0xffffffffu, p, off);
            float y = p + b2s[o];
            if (o == lane)      ya = y;
            if (o == lane + 32) yb = y;
        }
        // max over 40 logits (lanes >= 8 have no second logit)
        float cand = fmaxf(ya, lane < 8 ? yb : -INFINITY);
        #pragma unroll
        for (int off = 16; off; off >>= 1)
            cand = fmaxf(cand, __shfl_xor_sync(0xffffffffu, cand, off));
        float m = cand;
        float sp = expf(ya - m) + (lane < 8 ? expf(yb - m) : 0.f);
        #pragma unroll
        for (int off = 16; off; off >>= 1) sp += __shfl_xor_sync(0xffffffffu, sp, off);
        float ls = logf(sp);
        out[(size_t)n * OD + lane] = ya - m - ls;
        if (lane < 8) out[(size_t)n * OD + 32 + lane] = yb - m - ls;
    }
}

// ---------------- orchestration ---------------------------------------------
static void* sym_addr(const void* sym) {
    void* p = nullptr;
    cudaGetSymbolAddress(&p, sym);
    return p;
}

extern "C" void kernel_launch(void* const* d_in, const int* in_sizes, int n_in,
                              void* d_out, int out_size) {
    const float* x     = (const float*)d_in[0];
    const void*  eidx  = d_in[1];
    const float* W1    = (const float*)d_in[2];
    const float* b1    = (const float*)d_in[3];
    const float* att1  = (const float*)d_in[4];
    const float* bias1 = (const float*)d_in[5];
    const float* W2    = (const float*)d_in[6];
    const float* b2    = (const float*)d_in[7];
    const float* att2  = (const float*)d_in[8];
    const float* bias2 = (const float*)d_in[9];
    const float* Wp1   = (const float*)d_in[10];
    const float* bp1   = (const float*)d_in[11];
    const float* Wp2   = (const float*)d_in[12];
    const float* bp2   = (const float*)d_in[13];
    float* out = (float*)d_out;

    float* p_h   = (float*)sym_addr(g_h);
    float* p_agg = (float*)sym_addr(g_agg);
    float* p_wt  = (float*)sym_addr(g_wt);

    const int GEMM_SMEM = (128 * 132 + 128 * 128) * 4;
    cudaFuncSetAttribute(k_gemm, cudaFuncAttributeMaxDynamicSharedMemorySize, GEMM_SMEM);

    const int gemm_blocks = (NN + 127) / 128;        // 782
    const int edge_blocks = (NE + 255) / 256;        // 3907
    const int e3_blocks   = NE / 8;                  // 125000 (warp per edge)

    k_detect<<<1, 256>>>((const int*)eidx);

    // ---- layer 1 ----
    k_transpose<<<64, 256>>>(W1, p_wt);
    k_gemm<<<gemm_blocks, 256, GEMM_SMEM>>>(x, p_wt, b1, p_h, NN);
    k_prep<<<1024, 256>>>(p_h, att1);
    k_e1<<<edge_blocks, 256>>>(eidx);
    k_e2<<<edge_blocks, 256>>>(eidx);
    k_e3<<<e3_blocks, 256>>>(eidx, p_h);
    k_finalize<<<(NN * HD / 4 + 255) / 256, 256>>>(bias1);

    // ---- layer 2 ----
    k_transpose<<<64, 256>>>(W2, p_wt);
    k_gemm<<<gemm_blocks, 256, GEMM_SMEM>>>(p_agg, p_wt, b2, p_h, NN);
    k_prep<<<1024, 256>>>(p_h, att2);
    k_e1<<<edge_blocks, 256>>>(eidx);
    k_e2<<<edge_blocks, 256>>>(eidx);
    k_e3<<<e3_blocks, 256>>>(eidx, p_h);
    k_finalize<<<(NN * HD / 4 + 255) / 256, 256>>>(bias2);

    // ---- projection head ----
    k_transpose<<<64, 256>>>(Wp1, p_wt);
    k_gemm<<<gemm_blocks, 256, GEMM_SMEM>>>(p_agg, p_wt, bp1, p_h, NN);
    k_out<<<2048, 256>>>(p_h, Wp2, bp2, out);
}